// round 3
// baseline (speedup 1.0000x reference)
#include <cuda_runtime.h>
#include <cstdint>

// Problem constants
constexpr int NN   = 50000;   // nodes
constexpr int NE   = 800000;  // edges
constexpr int FIN  = 128;
constexpr int FHID = 256;
constexpr int FOUT = 128;

// ---------------- scratch (__device__ globals, 16B-aligned for float4 use) --
__device__ __align__(16) int   g_deg[NN];
__device__ __align__(16) float g_dinv[NN];
__device__ __align__(16) float g_agg1[(size_t)NN * FIN];   // A_norm @ x
__device__ __align__(16) float g_h1  [(size_t)NN * FHID];  // relu(agg1 @ W1 + b1)
__device__ __align__(16) float g_t2  [(size_t)NN * FOUT];  // h1 @ W2

// ---------------- small kernels ---------------------------------------------
__global__ void k_zero_deg() {
    int i = blockIdx.x * blockDim.x + threadIdx.x;
    if (i < NN) g_deg[i] = 0;
}

__global__ void k_count_deg(const int* __restrict__ dst) {
    int e = blockIdx.x * blockDim.x + threadIdx.x;
    if (e >= NE) return;
    int d = dst[e];
    if ((unsigned)d < (unsigned)NN) atomicAdd(&g_deg[d], 1);
}

__global__ void k_dinv() {
    int i = blockIdx.x * blockDim.x + threadIdx.x;
    if (i < NN) g_dinv[i] = rsqrtf((float)(g_deg[i] + 1));  // +1 self loop
}

// Layer-1 self-loop init: g_agg1[i,f] = x[i,f] * dinv[i]^2
__global__ void k_init_l1(const float* __restrict__ x) {
    int idx = blockIdx.x * blockDim.x + threadIdx.x;     // over NN*FIN/4
    const int F4 = FIN / 4;
    if (idx >= NN * F4) return;
    int node = idx / F4;
    float di = g_dinv[node];
    float s  = di * di;
    float4 v = ((const float4*)x)[idx];
    v.x *= s; v.y *= s; v.z *= s; v.w *= s;
    ((float4*)g_agg1)[idx] = v;
}

// Layer-2 self-loop init: out[i,f] = g_t2[i,f] * dinv[i]^2 + b2[f]
__global__ void k_init_l2(float* __restrict__ out, const float* __restrict__ b2) {
    int idx = blockIdx.x * blockDim.x + threadIdx.x;     // over NN*FOUT/4
    const int F4 = FOUT / 4;
    if (idx >= NN * F4) return;
    int node = idx / F4;
    int f4   = idx - node * F4;
    float di = g_dinv[node];
    float s  = di * di;
    float4 v = ((const float4*)g_t2)[idx];
    float4 b = ((const float4*)b2)[f4];
    v.x = v.x * s + b.x; v.y = v.y * s + b.y;
    v.z = v.z * s + b.z; v.w = v.w * s + b.w;
    ((float4*)out)[idx] = v;
}

// Layer-1 edge scatter: g_agg1[dst] += x[src] * dinv[src]*dinv[dst]; warp/edge
__global__ void k_scatter_l1(const float* __restrict__ x,
                             const int* __restrict__ src,
                             const int* __restrict__ dst) {
    int idx  = blockIdx.x * blockDim.x + threadIdx.x;
    int e    = idx >> 5;
    int lane = idx & 31;
    if (e >= NE) return;
    int s = src[e];
    int d = dst[e];
    if ((unsigned)s >= (unsigned)NN || (unsigned)d >= (unsigned)NN) return;
    float nrm = g_dinv[s] * g_dinv[d];
    float4 v = ((const float4*)(x + (size_t)s * FIN))[lane];
    float* p = g_agg1 + (size_t)d * FIN + lane * 4;
    atomicAdd(p + 0, v.x * nrm);
    atomicAdd(p + 1, v.y * nrm);
    atomicAdd(p + 2, v.z * nrm);
    atomicAdd(p + 3, v.w * nrm);
}

// Layer-2 edge scatter: out[dst] += g_t2[src] * dinv[src]*dinv[dst]; warp/edge
__global__ void k_scatter_l2(float* __restrict__ out,
                             const int* __restrict__ src,
                             const int* __restrict__ dst) {
    int idx  = blockIdx.x * blockDim.x + threadIdx.x;
    int e    = idx >> 5;
    int lane = idx & 31;
    if (e >= NE) return;
    int s = src[e];
    int d = dst[e];
    if ((unsigned)s >= (unsigned)NN || (unsigned)d >= (unsigned)NN) return;
    float nrm = g_dinv[s] * g_dinv[d];
    float4 v = ((const float4*)(g_t2 + (size_t)s * FOUT))[lane];
    float* p = out + (size_t)d * FOUT + lane * 4;
    atomicAdd(p + 0, v.x * nrm);
    atomicAdd(p + 1, v.y * nrm);
    atomicAdd(p + 2, v.z * nrm);
    atomicAdd(p + 3, v.w * nrm);
}

__global__ void k_relu(float* __restrict__ p, int n4) {
    int i = blockIdx.x * blockDim.x + threadIdx.x;
    if (i >= n4) return;
    float4 v = ((float4*)p)[i];
    v.x = fmaxf(v.x, 0.f); v.y = fmaxf(v.y, 0.f);
    v.z = fmaxf(v.z, 0.f); v.w = fmaxf(v.w, 0.f);
    ((float4*)p)[i] = v;
}

// ---------------- fp32 SGEMM over device-global A/C --------------------------
// LAYER1: g_h1[NN,FHID] = relu(g_agg1[NN,FIN] @ W1 + b1)
// LAYER2: g_t2[NN,FOUT] = g_h1[NN,FHID] @ W2
// BM=BN=128, BK=8, 256 threads, 8x8 per thread.
template <bool LAYER1>
__global__ __launch_bounds__(256)
void sgemm_kernel(const float* __restrict__ B, const float* __restrict__ bias) {
    constexpr int BM = 128, BN = 128, BK = 8, TM = 8, TN = 8;
    const int M = NN;
    const int N = LAYER1 ? FHID : FOUT;
    const int K = LAYER1 ? FIN  : FHID;
    const float* __restrict__ A = LAYER1 ? g_agg1 : g_h1;
    float* __restrict__       C = LAYER1 ? g_h1   : g_t2;

    __shared__ float As[BK][BM];
    __shared__ float Bs[BK][BN];

    int tid = threadIdx.x;
    int block_row = blockIdx.y * BM;
    int block_col = blockIdx.x * BN;

    int a_row = tid >> 1;           // 0..127
    int a_col = (tid & 1) * 4;      // 0 or 4
    int b_row = tid >> 5;           // 0..7
    int b_col = (tid & 31) * 4;     // 0..124

    int ty = tid >> 4;              // 0..15
    int tx = tid & 15;              // 0..15

    float acc[TM][TN];
    #pragma unroll
    for (int i = 0; i < TM; i++)
        #pragma unroll
        for (int j = 0; j < TN; j++) acc[i][j] = 0.f;

    for (int k0 = 0; k0 < K; k0 += BK) {
        int grow = block_row + a_row;
        float4 av = make_float4(0.f, 0.f, 0.f, 0.f);
        if (grow < M) av = *(const float4*)&A[(size_t)grow * K + k0 + a_col];
        As[a_col + 0][a_row] = av.x;
        As[a_col + 1][a_row] = av.y;
        As[a_col + 2][a_row] = av.z;
        As[a_col + 3][a_row] = av.w;
        float4 bv = *(const float4*)&B[(size_t)(k0 + b_row) * N + block_col + b_col];
        *(float4*)&Bs[b_row][b_col] = bv;
        __syncthreads();

        #pragma unroll
        for (int k = 0; k < BK; k++) {
            float ra[TM], rb[TN];
            #pragma unroll
            for (int i = 0; i < TM; i++) ra[i] = As[k][ty * TM + i];
            #pragma unroll
            for (int j = 0; j < TN; j++) rb[j] = Bs[k][tx * TN + j];
            #pragma unroll
            for (int i = 0; i < TM; i++)
                #pragma unroll
                for (int j = 0; j < TN; j++) acc[i][j] += ra[i] * rb[j];
        }
        __syncthreads();
    }

    #pragma unroll
    for (int i = 0; i < TM; i++) {
        int row = block_row + ty * TM + i;
        if (row >= M) continue;
        #pragma unroll
        for (int j = 0; j < TN; j += 4) {
            int col = block_col + tx * TN + j;
            float4 v = make_float4(acc[i][j], acc[i][j+1], acc[i][j+2], acc[i][j+3]);
            if (LAYER1) {
                v.x += bias[col];   v.y += bias[col+1];
                v.z += bias[col+2]; v.w += bias[col+3];
                v.x = fmaxf(v.x, 0.f); v.y = fmaxf(v.y, 0.f);
                v.z = fmaxf(v.z, 0.f); v.w = fmaxf(v.w, 0.f);
            }
            *(float4*)&C[(size_t)row * N + col] = v;
        }
    }
}

// ---------------- launch ------------------------------------------------------
extern "C" void kernel_launch(void* const* d_in, const int* in_sizes, int n_in,
                              void* d_out, int out_size) {
    const float* x  = (const float*)d_in[0];
    const int*   ei = (const int*)d_in[1];    // int32! (JAX x64 disabled)
    const float* W1 = (const float*)d_in[2];
    const float* b1 = (const float*)d_in[3];
    const float* W2 = (const float*)d_in[4];
    const float* b2 = (const float*)d_in[5];
    float* out = (float*)d_out;

    const int* srcp = ei;        // edge_index[0]
    const int* dstp = ei + NE;   // edge_index[1]

    const int T = 256;

    // degrees + normalization
    k_zero_deg <<<(NN + T - 1) / T, T>>>();
    k_count_deg<<<(NE + T - 1) / T, T>>>(dstp);
    k_dinv     <<<(NN + T - 1) / T, T>>>();

    // ---- layer 1: agg1 = A_norm @ x ; h1 = relu(agg1 @ W1 + b1) ----
    k_init_l1   <<<(NN * (FIN/4) + T - 1) / T, T>>>(x);
    k_scatter_l1<<<(NE * 32 + T - 1) / T, T>>>(x, srcp, dstp);
    {
        dim3 grid(FHID / 128, (NN + 127) / 128);
        sgemm_kernel<true><<<grid, 256>>>(W1, b1);
    }

    // ---- layer 2: t2 = h1 @ W2 ; out = relu(A_norm @ t2 + b2) ----
    {
        dim3 grid(FOUT / 128, (NN + 127) / 128);
        sgemm_kernel<false><<<grid, 256>>>(W2, nullptr);
    }
    k_init_l2   <<<(NN * (FOUT/4) + T - 1) / T, T>>>(out, b2);
    k_scatter_l2<<<(NE * 32 + T - 1) / T, T>>>(out, srcp, dstp);
    k_relu      <<<(NN * FOUT / 4 + T - 1) / T, T>>>(out, NN * FOUT / 4);
}

// round 4
// speedup vs baseline: 2.1976x; 2.1976x over previous
#include <cuda_runtime.h>
#include <cstdint>

// Problem constants
constexpr int NN   = 50000;   // nodes
constexpr int NE   = 800000;  // edges
constexpr int FIN  = 128;
constexpr int FHID = 256;
constexpr int FOUT = 128;

// ---------------- scratch (__device__ globals, 16B-aligned) -----------------
__device__ __align__(16) int   g_deg[NN];
__device__ __align__(16) float g_dinv[NN];
__device__ __align__(16) float g_agg1[(size_t)NN * FIN];   // A_norm @ x
__device__ __align__(16) float g_h1  [(size_t)NN * FHID];  // relu(agg1 @ W1 + b1)
__device__ __align__(16) float g_t2  [(size_t)NN * FOUT];  // h1 @ W2 (raw)

// ---------------- small kernels ---------------------------------------------
__global__ void k_zero_deg() {
    int i = blockIdx.x * blockDim.x + threadIdx.x;
    if (i < NN) g_deg[i] = 0;
}

__global__ void k_count_deg(const int* __restrict__ dst) {
    int e = blockIdx.x * blockDim.x + threadIdx.x;
    if (e >= NE) return;
    int d = dst[e];
    if ((unsigned)d < (unsigned)NN) atomicAdd(&g_deg[d], 1);
}

__global__ void k_dinv() {
    int i = blockIdx.x * blockDim.x + threadIdx.x;
    if (i < NN) g_dinv[i] = rsqrtf((float)(g_deg[i] + 1));  // +1 self loop
}

// Layer-1 self-loop init: g_agg1[i,f] = x[i,f] * dinv[i]^2
__global__ void k_init_l1(const float* __restrict__ x) {
    int idx = blockIdx.x * blockDim.x + threadIdx.x;     // over NN*FIN/4
    const int F4 = FIN / 4;
    if (idx >= NN * F4) return;
    int node = idx / F4;
    float di = g_dinv[node];
    float s  = di * di;
    float4 v = ((const float4*)x)[idx];
    v.x *= s; v.y *= s; v.z *= s; v.w *= s;
    ((float4*)g_agg1)[idx] = v;
}

// vectorized no-return global reduction (sm_90+)
__device__ __forceinline__ void red_add_v4(float* p, float a, float b, float c, float d) {
    asm volatile("red.global.add.v4.f32 [%0], {%1, %2, %3, %4};"
                 :: "l"(p), "f"(a), "f"(b), "f"(c), "f"(d) : "memory");
}

// Layer-1 edge scatter: g_agg1[dst] += x[src] * dinv[src]*dinv[dst]; warp/edge
__global__ void k_scatter_l1(const float* __restrict__ x,
                             const int* __restrict__ src,
                             const int* __restrict__ dst) {
    int idx  = blockIdx.x * blockDim.x + threadIdx.x;
    int e    = idx >> 5;
    int lane = idx & 31;
    if (e >= NE) return;
    int s = src[e];
    int d = dst[e];
    if ((unsigned)s >= (unsigned)NN || (unsigned)d >= (unsigned)NN) return;
    float nrm = g_dinv[s] * g_dinv[d];
    float4 v = ((const float4*)(x + (size_t)s * FIN))[lane];
    float* p = g_agg1 + (size_t)d * FIN + lane * 4;
    red_add_v4(p, v.x * nrm, v.y * nrm, v.z * nrm, v.w * nrm);
}

// Layer-2 edge scatter: out[dst] += g_t2[src] * dinv[src]*dinv[dst]; warp/edge
__global__ void k_scatter_l2(float* __restrict__ out,
                             const int* __restrict__ src,
                             const int* __restrict__ dst) {
    int idx  = blockIdx.x * blockDim.x + threadIdx.x;
    int e    = idx >> 5;
    int lane = idx & 31;
    if (e >= NE) return;
    int s = src[e];
    int d = dst[e];
    if ((unsigned)s >= (unsigned)NN || (unsigned)d >= (unsigned)NN) return;
    float nrm = g_dinv[s] * g_dinv[d];
    float4 v = ((const float4*)(g_t2 + (size_t)s * FOUT))[lane];
    float* p = out + (size_t)d * FOUT + lane * 4;
    red_add_v4(p, v.x * nrm, v.y * nrm, v.z * nrm, v.w * nrm);
}

__global__ void k_relu(float* __restrict__ p, int n4) {
    int i = blockIdx.x * blockDim.x + threadIdx.x;
    if (i >= n4) return;
    float4 v = ((float4*)p)[i];
    v.x = fmaxf(v.x, 0.f); v.y = fmaxf(v.y, 0.f);
    v.z = fmaxf(v.z, 0.f); v.w = fmaxf(v.w, 0.f);
    ((float4*)p)[i] = v;
}

// ---------------- tf32 tensor-core GEMM --------------------------------------
// LAYER1: g_h1 = relu(g_agg1[NN,128] @ W1[128,256] + b1)
// LAYER2: g_t2 = g_h1[NN,256] @ W2[256,128];  out = t2*dinv^2 + b2 (fused)
// 256 threads = 8 warps (2x4), block tile 128x128, BK=16, warp tile 64x32,
// mma.m16n8k8.tf32 with fp32 accumulate.

__device__ __forceinline__ unsigned f2tf(float f) {
    unsigned u;
    asm("cvt.rna.tf32.f32 %0, %1;" : "=r"(u) : "f"(f));
    return u;
}

template <bool LAYER1>
__global__ __launch_bounds__(256)
void mma_gemm(const float* __restrict__ B, const float* __restrict__ bias,
              float* __restrict__ out2) {
    constexpr int N  = LAYER1 ? FHID : FOUT;
    constexpr int K  = LAYER1 ? FIN  : FHID;
    constexpr int BM = 128, BK = 16;
    constexpr int APITCH = 20;    // floats per A smem row (conflict-free frag loads)
    constexpr int BPITCH = 136;   // floats per B smem row (conflict-free frag loads)
    const float* __restrict__ A = LAYER1 ? g_agg1 : g_h1;
    float* __restrict__       C = LAYER1 ? g_h1   : g_t2;

    __shared__ unsigned As[BM * APITCH];   // [m][k], tf32 bits
    __shared__ unsigned Bs[BK * BPITCH];   // [k][n], tf32 bits

    int tid  = threadIdx.x;
    int lane = tid & 31;
    int wid  = tid >> 5;
    int warp_m = wid >> 2;        // 0..1
    int warp_n = wid & 3;         // 0..3
    int block_row = blockIdx.y * BM;
    int block_col = blockIdx.x * 128;

    float acc[4][4][4];           // [mt][nt][c0..c3]
    #pragma unroll
    for (int i = 0; i < 4; i++)
        #pragma unroll
        for (int j = 0; j < 4; j++)
            #pragma unroll
            for (int c = 0; c < 4; c++) acc[i][j][c] = 0.f;

    for (int k0 = 0; k0 < K; k0 += BK) {
        // stage A tile: 128 rows x 16 k
        #pragma unroll
        for (int it = 0; it < 2; it++) {
            int r = (tid >> 2) + it * 64;
            int q = (tid & 3) * 4;
            int grow = block_row + r;
            float4 av = make_float4(0.f, 0.f, 0.f, 0.f);
            if (grow < NN) av = *(const float4*)&A[(size_t)grow * K + k0 + q];
            unsigned* dp = &As[r * APITCH + q];
            dp[0] = f2tf(av.x); dp[1] = f2tf(av.y);
            dp[2] = f2tf(av.z); dp[3] = f2tf(av.w);
        }
        // stage B tile: 16 k x 128 n
        #pragma unroll
        for (int it = 0; it < 2; it++) {
            int kr = (tid >> 5) + it * 8;
            int c  = (tid & 31) * 4;
            float4 bv = *(const float4*)&B[(size_t)(k0 + kr) * N + block_col + c];
            unsigned* dp = &Bs[kr * BPITCH + c];
            dp[0] = f2tf(bv.x); dp[1] = f2tf(bv.y);
            dp[2] = f2tf(bv.z); dp[3] = f2tf(bv.w);
        }
        __syncthreads();

        #pragma unroll
        for (int ks = 0; ks < 2; ks++) {
            int kk = ks * 8;
            unsigned af[4][4], bf[4][2];
            #pragma unroll
            for (int mt = 0; mt < 4; mt++) {
                int r = warp_m * 64 + mt * 16 + (lane >> 2);
                int kc = kk + (lane & 3);
                af[mt][0] = As[r * APITCH + kc];
                af[mt][1] = As[(r + 8) * APITCH + kc];
                af[mt][2] = As[r * APITCH + kc + 4];
                af[mt][3] = As[(r + 8) * APITCH + kc + 4];
            }
            #pragma unroll
            for (int nt = 0; nt < 4; nt++) {
                int c = warp_n * 32 + nt * 8 + (lane >> 2);
                bf[nt][0] = Bs[(kk + (lane & 3)) * BPITCH + c];
                bf[nt][1] = Bs[(kk + (lane & 3) + 4) * BPITCH + c];
            }
            #pragma unroll
            for (int mt = 0; mt < 4; mt++)
                #pragma unroll
                for (int nt = 0; nt < 4; nt++)
                    asm volatile(
                        "mma.sync.aligned.m16n8k8.row.col.f32.tf32.tf32.f32 "
                        "{%0,%1,%2,%3}, {%4,%5,%6,%7}, {%8,%9}, {%0,%1,%2,%3};"
                        : "+f"(acc[mt][nt][0]), "+f"(acc[mt][nt][1]),
                          "+f"(acc[mt][nt][2]), "+f"(acc[mt][nt][3])
                        : "r"(af[mt][0]), "r"(af[mt][1]),
                          "r"(af[mt][2]), "r"(af[mt][3]),
                          "r"(bf[nt][0]), "r"(bf[nt][1]));
        }
        __syncthreads();
    }

    // epilogue
    #pragma unroll
    for (int mt = 0; mt < 4; mt++) {
        int r0 = block_row + warp_m * 64 + mt * 16 + (lane >> 2);
        #pragma unroll
        for (int half = 0; half < 2; half++) {
            int row = r0 + half * 8;
            if (row >= NN) continue;
            float dsc = 0.f;
            if (!LAYER1) { float di = g_dinv[row]; dsc = di * di; }
            #pragma unroll
            for (int nt = 0; nt < 4; nt++) {
                int col = block_col + warp_n * 32 + nt * 8 + (lane & 3) * 2;
                float v0 = acc[mt][nt][half * 2 + 0];
                float v1 = acc[mt][nt][half * 2 + 1];
                if (LAYER1) {
                    v0 = fmaxf(v0 + bias[col],     0.f);
                    v1 = fmaxf(v1 + bias[col + 1], 0.f);
                    *(float2*)&C[(size_t)row * N + col] = make_float2(v0, v1);
                } else {
                    *(float2*)&C[(size_t)row * N + col] = make_float2(v0, v1);
                    float o0 = v0 * dsc + bias[col];
                    float o1 = v1 * dsc + bias[col + 1];
                    *(float2*)&out2[(size_t)row * N + col] = make_float2(o0, o1);
                }
            }
        }
    }
}

// ---------------- launch ------------------------------------------------------
extern "C" void kernel_launch(void* const* d_in, const int* in_sizes, int n_in,
                              void* d_out, int out_size) {
    const float* x  = (const float*)d_in[0];
    const int*   ei = (const int*)d_in[1];    // int32 (JAX x64 disabled)
    const float* W1 = (const float*)d_in[2];
    const float* b1 = (const float*)d_in[3];
    const float* W2 = (const float*)d_in[4];
    const float* b2 = (const float*)d_in[5];
    float* out = (float*)d_out;

    const int* srcp = ei;        // edge_index[0]
    const int* dstp = ei + NE;   // edge_index[1]

    const int T = 256;
    const int MBLK = (NN + 127) / 128;   // 391

    // degrees + normalization
    k_zero_deg <<<(NN + T - 1) / T, T>>>();
    k_count_deg<<<(NE + T - 1) / T, T>>>(dstp);
    k_dinv     <<<(NN + T - 1) / T, T>>>();

    // ---- layer 1: agg1 = A_norm @ x ; h1 = relu(agg1 @ W1 + b1) ----
    k_init_l1   <<<(NN * (FIN/4) + T - 1) / T, T>>>(x);
    k_scatter_l1<<<(NE * 32 + T - 1) / T, T>>>(x, srcp, dstp);
    {
        dim3 grid(FHID / 128, MBLK);
        mma_gemm<true><<<grid, 256>>>(W1, b1, nullptr);
    }

    // ---- layer 2: t2 = h1 @ W2 ; out(init) = t2*dinv^2 + b2 (fused epilogue) ----
    {
        dim3 grid(FOUT / 128, MBLK);
        mma_gemm<false><<<grid, 256>>>(W2, b2, out);
    }
    k_scatter_l2<<<(NE * 32 + T - 1) / T, T>>>(out, srcp, dstp);
    k_relu      <<<(NN * FOUT / 4 + T - 1) / T, T>>>(out, NN * FOUT / 4);
}

// round 7
// speedup vs baseline: 3.4174x; 1.5551x over previous
#include <cuda_runtime.h>
#include <cstdint>

// Problem constants
constexpr int NN   = 50000;   // nodes
constexpr int NE   = 800000;  // edges
constexpr int FIN  = 128;
constexpr int FHID = 256;
constexpr int FOUT = 128;

// ---------------- scratch (__device__ globals; referenced ONLY in device code)
__device__ __align__(16) int   g_deg[NN];
__device__ __align__(16) int   g_cursor[NN];
__device__ __align__(16) int   g_off[NN + 1];
__device__ __align__(16) int   g_esrc[NE];                 // CSR: src per (dst-grouped) edge
__device__ __align__(16) float g_dinv[NN];
__device__ __align__(16) float g_agg1[(size_t)NN * FIN];   // A_norm @ x
__device__ __align__(16) float g_h1  [(size_t)NN * FHID];  // relu(agg1 @ W1 + b1)
__device__ __align__(16) float g_t2  [(size_t)NN * FOUT];  // h1 @ W2 (raw)

// ---------------- CSR build --------------------------------------------------
__global__ void k_zero() {
    int i = blockIdx.x * blockDim.x + threadIdx.x;
    if (i < NN) { g_deg[i] = 0; g_cursor[i] = 0; }
}

__global__ void k_count_deg(const int* __restrict__ dst) {
    int e = blockIdx.x * blockDim.x + threadIdx.x;
    if (e >= NE) return;
    int d = dst[e];
    if ((unsigned)d < (unsigned)NN) atomicAdd(&g_deg[d], 1);
}

__global__ void k_dinv() {
    int i = blockIdx.x * blockDim.x + threadIdx.x;
    if (i < NN) g_dinv[i] = rsqrtf((float)(g_deg[i] + 1));  // +1 self loop
}

// single-block exclusive scan of g_deg -> g_off (1024 threads)
__global__ void k_scan() {
    __shared__ int wsum[32];
    __shared__ int carry_s;
    int tid = threadIdx.x, lane = tid & 31, wid = tid >> 5;
    if (tid == 0) carry_s = 0;
    __syncthreads();
    for (int base = 0; base < NN; base += 1024) {
        int i = base + tid;
        int v = (i < NN) ? g_deg[i] : 0;
        int x = v;
        #pragma unroll
        for (int o = 1; o < 32; o <<= 1) {
            int t = __shfl_up_sync(0xffffffffu, x, o);
            if (lane >= o) x += t;
        }
        if (lane == 31) wsum[wid] = x;
        __syncthreads();
        if (wid == 0) {
            int s = wsum[lane];
            #pragma unroll
            for (int o = 1; o < 32; o <<= 1) {
                int t = __shfl_up_sync(0xffffffffu, s, o);
                if (lane >= o) s += t;
            }
            wsum[lane] = s;          // inclusive scan of warp sums
        }
        __syncthreads();
        int wprefix = (wid == 0) ? 0 : wsum[wid - 1];
        int excl = carry_s + wprefix + x - v;
        if (i < NN) g_off[i] = excl;
        __syncthreads();             // everyone has read carry_s
        if (tid == 1023) carry_s += wsum[31];
        __syncthreads();
    }
    if (threadIdx.x == 0) g_off[NN] = carry_s;
}

__global__ void k_fill(const int* __restrict__ src, const int* __restrict__ dst) {
    int e = blockIdx.x * blockDim.x + threadIdx.x;
    if (e >= NE) return;
    int d = dst[e];
    int s = src[e];
    if ((unsigned)d >= (unsigned)NN || (unsigned)s >= (unsigned)NN) return;
    int pos = g_off[d] + atomicAdd(&g_cursor[d], 1);
    g_esrc[pos] = s;
}

// ---------------- gather-aggregate (warp per destination) --------------------
// LAYER2=false: g_agg1[d] = xin[d]*dinv[d]^2 + sum_in xin[s]*dinv[s]dinv[d]
// LAYER2=true : outp[d]  = relu( g_t2[d]*dinv^2 + sum_in g_t2[s]*dinv[s]dinv[d] + bias )
// All __device__ globals selected INSIDE the kernel (never passed from host).
template <bool LAYER2>
__global__ __launch_bounds__(256)
void k_aggr(const float* __restrict__ xin, const float* __restrict__ bias,
            float* __restrict__ outp) {
    const float* __restrict__ feat = LAYER2 ? g_t2 : xin;
    float* __restrict__       dstp = LAYER2 ? outp : g_agg1;

    int gw   = (blockIdx.x * blockDim.x + threadIdx.x) >> 5;   // node
    int lane = threadIdx.x & 31;
    if (gw >= NN) return;
    float dd = g_dinv[gw];
    float s2 = dd * dd;
    float4 a = ((const float4*)(feat + (size_t)gw * 128))[lane];
    float4 acc = make_float4(a.x * s2, a.y * s2, a.z * s2, a.w * s2);

    int i   = g_off[gw];
    int end = g_off[gw + 1];
    for (; i + 1 < end; i += 2) {
        int s0 = g_esrc[i];
        int s1 = g_esrc[i + 1];
        float n0 = g_dinv[s0] * dd;
        float n1 = g_dinv[s1] * dd;
        float4 v0 = ((const float4*)(feat + (size_t)s0 * 128))[lane];
        float4 v1 = ((const float4*)(feat + (size_t)s1 * 128))[lane];
        acc.x += v0.x * n0; acc.y += v0.y * n0;
        acc.z += v0.z * n0; acc.w += v0.w * n0;
        acc.x += v1.x * n1; acc.y += v1.y * n1;
        acc.z += v1.z * n1; acc.w += v1.w * n1;
    }
    if (i < end) {
        int s0 = g_esrc[i];
        float n0 = g_dinv[s0] * dd;
        float4 v0 = ((const float4*)(feat + (size_t)s0 * 128))[lane];
        acc.x += v0.x * n0; acc.y += v0.y * n0;
        acc.z += v0.z * n0; acc.w += v0.w * n0;
    }
    if (LAYER2) {
        float4 b = ((const float4*)bias)[lane];
        acc.x = fmaxf(acc.x + b.x, 0.f); acc.y = fmaxf(acc.y + b.y, 0.f);
        acc.z = fmaxf(acc.z + b.z, 0.f); acc.w = fmaxf(acc.w + b.w, 0.f);
    }
    ((float4*)(dstp + (size_t)gw * 128))[lane] = acc;
}

// ---------------- tf32 tensor-core GEMM (register double-buffered) -----------
// LAYER1: g_h1 = relu(g_agg1[NN,128] @ W1[128,256] + b1)
// LAYER2: g_t2 = g_h1[NN,256] @ W2[256,128]
__device__ __forceinline__ unsigned f2tf(float f) {
    unsigned u;
    asm("cvt.rna.tf32.f32 %0, %1;" : "=r"(u) : "f"(f));
    return u;
}

template <bool LAYER1>
__global__ __launch_bounds__(256)
void mma_gemm(const float* __restrict__ B, const float* __restrict__ bias) {
    constexpr int N  = LAYER1 ? FHID : FOUT;
    constexpr int K  = LAYER1 ? FIN  : FHID;
    constexpr int BM = 128, BK = 16;
    constexpr int APITCH = 20;
    constexpr int BPITCH = 136;
    const float* __restrict__ A = LAYER1 ? g_agg1 : g_h1;
    float* __restrict__       C = LAYER1 ? g_h1   : g_t2;

    __shared__ unsigned As[BM * APITCH];   // [m][k], tf32 bits
    __shared__ unsigned Bs[BK * BPITCH];   // [k][n], tf32 bits

    int tid  = threadIdx.x;
    int lane = tid & 31;
    int wid  = tid >> 5;
    int warp_m = wid >> 2;        // 0..1
    int warp_n = wid & 3;         // 0..3
    int block_row = blockIdx.y * BM;
    int block_col = blockIdx.x * 128;

    int ar = tid >> 2;            // A row 0..63 (+64 for it=1)
    int aq = (tid & 3) * 4;       // A k-col
    int bkr = tid >> 5;           // B k-row 0..7 (+8 for it=1)
    int bc  = (tid & 31) * 4;     // B n-col

    auto loadA = [&](int k0, int it) -> float4 {
        int grow = block_row + ar + it * 64;
        if (grow < NN) return *(const float4*)&A[(size_t)grow * K + k0 + aq];
        return make_float4(0.f, 0.f, 0.f, 0.f);
    };
    auto loadB = [&](int k0, int it) -> float4 {
        return *(const float4*)&B[(size_t)(k0 + bkr + it * 8) * N + block_col + bc];
    };

    float acc[4][4][4];
    #pragma unroll
    for (int i = 0; i < 4; i++)
        #pragma unroll
        for (int j = 0; j < 4; j++)
            #pragma unroll
            for (int c = 0; c < 4; c++) acc[i][j][c] = 0.f;

    float4 a_pre[2], b_pre[2];
    a_pre[0] = loadA(0, 0); a_pre[1] = loadA(0, 1);
    b_pre[0] = loadB(0, 0); b_pre[1] = loadB(0, 1);

    for (int k0 = 0; k0 < K; k0 += BK) {
        #pragma unroll
        for (int it = 0; it < 2; it++) {
            unsigned* dp = &As[(ar + it * 64) * APITCH + aq];
            dp[0] = f2tf(a_pre[it].x); dp[1] = f2tf(a_pre[it].y);
            dp[2] = f2tf(a_pre[it].z); dp[3] = f2tf(a_pre[it].w);
            unsigned* bp = &Bs[(bkr + it * 8) * BPITCH + bc];
            bp[0] = f2tf(b_pre[it].x); bp[1] = f2tf(b_pre[it].y);
            bp[2] = f2tf(b_pre[it].z); bp[3] = f2tf(b_pre[it].w);
        }
        __syncthreads();

        if (k0 + BK < K) {
            a_pre[0] = loadA(k0 + BK, 0); a_pre[1] = loadA(k0 + BK, 1);
            b_pre[0] = loadB(k0 + BK, 0); b_pre[1] = loadB(k0 + BK, 1);
        }

        #pragma unroll
        for (int ks = 0; ks < 2; ks++) {
            int kk = ks * 8;
            unsigned af[4][4], bf[4][2];
            #pragma unroll
            for (int mt = 0; mt < 4; mt++) {
                int r = warp_m * 64 + mt * 16 + (lane >> 2);
                int kc = kk + (lane & 3);
                af[mt][0] = As[r * APITCH + kc];
                af[mt][1] = As[(r + 8) * APITCH + kc];
                af[mt][2] = As[r * APITCH + kc + 4];
                af[mt][3] = As[(r + 8) * APITCH + kc + 4];
            }
            #pragma unroll
            for (int nt = 0; nt < 4; nt++) {
                int c = warp_n * 32 + nt * 8 + (lane >> 2);
                bf[nt][0] = Bs[(kk + (lane & 3)) * BPITCH + c];
                bf[nt][1] = Bs[(kk + (lane & 3) + 4) * BPITCH + c];
            }
            #pragma unroll
            for (int mt = 0; mt < 4; mt++)
                #pragma unroll
                for (int nt = 0; nt < 4; nt++)
                    asm volatile(
                        "mma.sync.aligned.m16n8k8.row.col.f32.tf32.tf32.f32 "
                        "{%0,%1,%2,%3}, {%4,%5,%6,%7}, {%8,%9}, {%0,%1,%2,%3};"
                        : "+f"(acc[mt][nt][0]), "+f"(acc[mt][nt][1]),
                          "+f"(acc[mt][nt][2]), "+f"(acc[mt][nt][3])
                        : "r"(af[mt][0]), "r"(af[mt][1]),
                          "r"(af[mt][2]), "r"(af[mt][3]),
                          "r"(bf[nt][0]), "r"(bf[nt][1]));
        }
        __syncthreads();
    }

    #pragma unroll
    for (int mt = 0; mt < 4; mt++) {
        int r0 = block_row + warp_m * 64 + mt * 16 + (lane >> 2);
        #pragma unroll
        for (int half = 0; half < 2; half++) {
            int row = r0 + half * 8;
            if (row >= NN) continue;
            #pragma unroll
            for (int nt = 0; nt < 4; nt++) {
                int col = block_col + warp_n * 32 + nt * 8 + (lane & 3) * 2;
                float v0 = acc[mt][nt][half * 2 + 0];
                float v1 = acc[mt][nt][half * 2 + 1];
                if (LAYER1) {
                    v0 = fmaxf(v0 + bias[col],     0.f);
                    v1 = fmaxf(v1 + bias[col + 1], 0.f);
                }
                *(float2*)&C[(size_t)row * N + col] = make_float2(v0, v1);
            }
        }
    }
}

// ---------------- launch ------------------------------------------------------
extern "C" void kernel_launch(void* const* d_in, const int* in_sizes, int n_in,
                              void* d_out, int out_size) {
    const float* x  = (const float*)d_in[0];
    const int*   ei = (const int*)d_in[1];    // int32 (JAX x64 disabled)
    const float* W1 = (const float*)d_in[2];
    const float* b1 = (const float*)d_in[3];
    const float* W2 = (const float*)d_in[4];
    const float* b2 = (const float*)d_in[5];
    float* out = (float*)d_out;

    const int* srcp = ei;        // edge_index[0]
    const int* dstp = ei + NE;   // edge_index[1]

    const int T = 256;
    const int MBLK = (NN + 127) / 128;   // 391
    const int AGGR_GRID = (NN * 32 + T - 1) / T;

    // CSR build + normalization
    k_zero     <<<(NN + T - 1) / T, T>>>();
    k_count_deg<<<(NE + T - 1) / T, T>>>(dstp);
    k_dinv     <<<(NN + T - 1) / T, T>>>();
    k_scan     <<<1, 1024>>>();
    k_fill     <<<(NE + T - 1) / T, T>>>(srcp, dstp);

    // layer 1: agg1 = A_norm @ x ; h1 = relu(agg1 @ W1 + b1)
    k_aggr<false><<<AGGR_GRID, T>>>(x, nullptr, nullptr);
    {
        dim3 grid(FHID / 128, MBLK);
        mma_gemm<true><<<grid, 256>>>(W1, b1);
    }

    // layer 2: t2 = h1 @ W2 ; out = relu(A_norm @ t2 + b2)
    {
        dim3 grid(FOUT / 128, MBLK);
        mma_gemm<false><<<grid, 256>>>(W2, nullptr);
    }
    k_aggr<true><<<AGGR_GRID, T>>>(nullptr, b2, out);
}

// round 8
// speedup vs baseline: 4.1426x; 1.2122x over previous
#include <cuda_runtime.h>
#include <cstdint>

// Problem constants
constexpr int NN   = 50000;   // nodes
constexpr int NE   = 800000;  // edges
constexpr int FIN  = 128;
constexpr int FHID = 256;
constexpr int FOUT = 128;
constexpr int NB   = (NN + 1023) / 1024;   // scan blocks = 49

// ---------------- scratch (__device__ globals; referenced ONLY in device code)
__device__ __align__(16) int   g_deg[NN];
__device__ __align__(16) int   g_cursor[NN];
__device__ __align__(16) int   g_off[NN + 1];
__device__ __align__(16) int   g_bsum[NB];                 // per-block sums
__device__ __align__(16) int   g_bpre[NB + 1];             // scanned block prefixes
__device__ __align__(16) int   g_esrc[NE];                 // CSR: src per (dst-grouped) edge
__device__ __align__(16) float g_dinv[NN];
__device__ __align__(16) float g_agg1[(size_t)NN * FIN];   // A_norm @ x
__device__ __align__(16) float g_h1  [(size_t)NN * FHID];  // relu(agg1 @ W1 + b1)
__device__ __align__(16) float g_t2  [(size_t)NN * FOUT];  // h1 @ W2 (raw)

// ---------------- CSR build --------------------------------------------------
__global__ void k_zero() {
    int i = blockIdx.x * blockDim.x + threadIdx.x;
    if (i < NN) { g_deg[i] = 0; g_cursor[i] = 0; }
}

__global__ void k_count_deg(const int* __restrict__ dst) {
    int e = blockIdx.x * blockDim.x + threadIdx.x;
    if (e >= NE) return;
    int d = dst[e];
    if ((unsigned)d < (unsigned)NN) atomicAdd(&g_deg[d], 1);
}

__global__ void k_dinv() {
    int i = blockIdx.x * blockDim.x + threadIdx.x;
    if (i < NN) g_dinv[i] = rsqrtf((float)(g_deg[i] + 1));  // +1 self loop
}

// Phase 1: per-block exclusive scan of g_deg, block sums to g_bsum
__global__ __launch_bounds__(1024)
void k_scan1() {
    __shared__ int wsum[32];
    int tid = threadIdx.x, lane = tid & 31, wid = tid >> 5;
    int i = blockIdx.x * 1024 + tid;
    int v = (i < NN) ? g_deg[i] : 0;
    int x = v;
    #pragma unroll
    for (int o = 1; o < 32; o <<= 1) {
        int t = __shfl_up_sync(0xffffffffu, x, o);
        if (lane >= o) x += t;
    }
    if (lane == 31) wsum[wid] = x;
    __syncthreads();
    if (wid == 0) {
        int s = wsum[lane];
        #pragma unroll
        for (int o = 1; o < 32; o <<= 1) {
            int t = __shfl_up_sync(0xffffffffu, s, o);
            if (lane >= o) s += t;
        }
        wsum[lane] = s;              // inclusive scan of warp sums
    }
    __syncthreads();
    int wprefix = (wid == 0) ? 0 : wsum[wid - 1];
    if (i < NN) g_off[i] = wprefix + x - v;     // block-local exclusive
    if (tid == 1023) g_bsum[blockIdx.x] = wsum[31];
}

// Phase 2: scan the 49 block sums (one block, 64 threads)
__global__ void k_scan2() {
    __shared__ int ws[2];
    int tid = threadIdx.x, lane = tid & 31, wid = tid >> 5;
    int v = (tid < NB) ? g_bsum[tid] : 0;
    int x = v;
    #pragma unroll
    for (int o = 1; o < 32; o <<= 1) {
        int t = __shfl_up_sync(0xffffffffu, x, o);
        if (lane >= o) x += t;
    }
    if (lane == 31) ws[wid] = x;
    __syncthreads();
    int pre = (wid == 1) ? ws[0] : 0;
    if (tid < NB) g_bpre[tid] = pre + x - v;    // exclusive
    if (tid == NB - 1) {
        g_bpre[NB] = pre + x;                   // total
        g_off[NN]  = pre + x;
    }
}

// Phase 3: add block prefixes
__global__ __launch_bounds__(1024)
void k_scan3() {
    int i = blockIdx.x * 1024 + threadIdx.x;
    if (i < NN) g_off[i] += g_bpre[blockIdx.x];
}

__global__ void k_fill(const int* __restrict__ src, const int* __restrict__ dst) {
    int e = blockIdx.x * blockDim.x + threadIdx.x;
    if (e >= NE) return;
    int d = dst[e];
    int s = src[e];
    if ((unsigned)d >= (unsigned)NN || (unsigned)s >= (unsigned)NN) return;
    int pos = g_off[d] + atomicAdd(&g_cursor[d], 1);
    g_esrc[pos] = s;
}

// ---------------- gather-aggregate (warp per destination) --------------------
// LAYER2=false: g_agg1[d] = xin[d]*dinv[d]^2 + sum_in xin[s]*dinv[s]dinv[d]
// LAYER2=true : outp[d]  = relu( g_t2[d]*dinv^2 + sum_in g_t2[s]*dinv[s]dinv[d] + bias )
template <bool LAYER2>
__global__ __launch_bounds__(256)
void k_aggr(const float* __restrict__ xin, const float* __restrict__ bias,
            float* __restrict__ outp) {
    const float* __restrict__ feat = LAYER2 ? g_t2 : xin;
    float* __restrict__       dstp = LAYER2 ? outp : g_agg1;

    int gw   = (blockIdx.x * blockDim.x + threadIdx.x) >> 5;   // node
    int lane = threadIdx.x & 31;
    if (gw >= NN) return;
    float dd = g_dinv[gw];
    float s2 = dd * dd;
    float4 a = ((const float4*)(feat + (size_t)gw * 128))[lane];
    float4 acc = make_float4(a.x * s2, a.y * s2, a.z * s2, a.w * s2);

    int i   = g_off[gw];
    int end = g_off[gw + 1];
    // unroll x4 for gather MLP
    for (; i + 3 < end; i += 4) {
        int s0 = g_esrc[i],     s1 = g_esrc[i + 1];
        int s2i = g_esrc[i + 2], s3 = g_esrc[i + 3];
        float n0 = g_dinv[s0] * dd, n1 = g_dinv[s1] * dd;
        float n2 = g_dinv[s2i] * dd, n3 = g_dinv[s3] * dd;
        float4 v0 = ((const float4*)(feat + (size_t)s0 * 128))[lane];
        float4 v1 = ((const float4*)(feat + (size_t)s1 * 128))[lane];
        float4 v2 = ((const float4*)(feat + (size_t)s2i * 128))[lane];
        float4 v3 = ((const float4*)(feat + (size_t)s3 * 128))[lane];
        acc.x += v0.x * n0; acc.y += v0.y * n0; acc.z += v0.z * n0; acc.w += v0.w * n0;
        acc.x += v1.x * n1; acc.y += v1.y * n1; acc.z += v1.z * n1; acc.w += v1.w * n1;
        acc.x += v2.x * n2; acc.y += v2.y * n2; acc.z += v2.z * n2; acc.w += v2.w * n2;
        acc.x += v3.x * n3; acc.y += v3.y * n3; acc.z += v3.z * n3; acc.w += v3.w * n3;
    }
    for (; i < end; i++) {
        int s0 = g_esrc[i];
        float n0 = g_dinv[s0] * dd;
        float4 v0 = ((const float4*)(feat + (size_t)s0 * 128))[lane];
        acc.x += v0.x * n0; acc.y += v0.y * n0; acc.z += v0.z * n0; acc.w += v0.w * n0;
    }
    if (LAYER2) {
        float4 b = ((const float4*)bias)[lane];
        acc.x = fmaxf(acc.x + b.x, 0.f); acc.y = fmaxf(acc.y + b.y, 0.f);
        acc.z = fmaxf(acc.z + b.z, 0.f); acc.w = fmaxf(acc.w + b.w, 0.f);
    }
    ((float4*)(dstp + (size_t)gw * 128))[lane] = acc;
}

// ---------------- tf32 tensor-core GEMM (register double-buffered) -----------
__device__ __forceinline__ unsigned f2tf(float f) {
    unsigned u;
    asm("cvt.rna.tf32.f32 %0, %1;" : "=r"(u) : "f"(f));
    return u;
}

template <bool LAYER1>
__global__ __launch_bounds__(256)
void mma_gemm(const float* __restrict__ B, const float* __restrict__ bias) {
    constexpr int N  = LAYER1 ? FHID : FOUT;
    constexpr int K  = LAYER1 ? FIN  : FHID;
    constexpr int BM = 128, BK = 16;
    constexpr int APITCH = 20;
    constexpr int BPITCH = 136;
    const float* __restrict__ A = LAYER1 ? g_agg1 : g_h1;
    float* __restrict__       C = LAYER1 ? g_h1   : g_t2;

    __shared__ unsigned As[BM * APITCH];
    __shared__ unsigned Bs[BK * BPITCH];

    int tid  = threadIdx.x;
    int lane = tid & 31;
    int wid  = tid >> 5;
    int warp_m = wid >> 2;
    int warp_n = wid & 3;
    int block_row = blockIdx.y * BM;
    int block_col = blockIdx.x * 128;

    int ar = tid >> 2;
    int aq = (tid & 3) * 4;
    int bkr = tid >> 5;
    int bc  = (tid & 31) * 4;

    auto loadA = [&](int k0, int it) -> float4 {
        int grow = block_row + ar + it * 64;
        if (grow < NN) return *(const float4*)&A[(size_t)grow * K + k0 + aq];
        return make_float4(0.f, 0.f, 0.f, 0.f);
    };
    auto loadB = [&](int k0, int it) -> float4 {
        return *(const float4*)&B[(size_t)(k0 + bkr + it * 8) * N + block_col + bc];
    };

    float acc[4][4][4];
    #pragma unroll
    for (int i = 0; i < 4; i++)
        #pragma unroll
        for (int j = 0; j < 4; j++)
            #pragma unroll
            for (int c = 0; c < 4; c++) acc[i][j][c] = 0.f;

    float4 a_pre[2], b_pre[2];
    a_pre[0] = loadA(0, 0); a_pre[1] = loadA(0, 1);
    b_pre[0] = loadB(0, 0); b_pre[1] = loadB(0, 1);

    for (int k0 = 0; k0 < K; k0 += BK) {
        #pragma unroll
        for (int it = 0; it < 2; it++) {
            unsigned* dp = &As[(ar + it * 64) * APITCH + aq];
            dp[0] = f2tf(a_pre[it].x); dp[1] = f2tf(a_pre[it].y);
            dp[2] = f2tf(a_pre[it].z); dp[3] = f2tf(a_pre[it].w);
            unsigned* bp = &Bs[(bkr + it * 8) * BPITCH + bc];
            bp[0] = f2tf(b_pre[it].x); bp[1] = f2tf(b_pre[it].y);
            bp[2] = f2tf(b_pre[it].z); bp[3] = f2tf(b_pre[it].w);
        }
        __syncthreads();

        if (k0 + BK < K) {
            a_pre[0] = loadA(k0 + BK, 0); a_pre[1] = loadA(k0 + BK, 1);
            b_pre[0] = loadB(k0 + BK, 0); b_pre[1] = loadB(k0 + BK, 1);
        }

        #pragma unroll
        for (int ks = 0; ks < 2; ks++) {
            int kk = ks * 8;
            unsigned af[4][4], bf[4][2];
            #pragma unroll
            for (int mt = 0; mt < 4; mt++) {
                int r = warp_m * 64 + mt * 16 + (lane >> 2);
                int kc = kk + (lane & 3);
                af[mt][0] = As[r * APITCH + kc];
                af[mt][1] = As[(r + 8) * APITCH + kc];
                af[mt][2] = As[r * APITCH + kc + 4];
                af[mt][3] = As[(r + 8) * APITCH + kc + 4];
            }
            #pragma unroll
            for (int nt = 0; nt < 4; nt++) {
                int c = warp_n * 32 + nt * 8 + (lane >> 2);
                bf[nt][0] = Bs[(kk + (lane & 3)) * BPITCH + c];
                bf[nt][1] = Bs[(kk + (lane & 3) + 4) * BPITCH + c];
            }
            #pragma unroll
            for (int mt = 0; mt < 4; mt++)
                #pragma unroll
                for (int nt = 0; nt < 4; nt++)
                    asm volatile(
                        "mma.sync.aligned.m16n8k8.row.col.f32.tf32.tf32.f32 "
                        "{%0,%1,%2,%3}, {%4,%5,%6,%7}, {%8,%9}, {%0,%1,%2,%3};"
                        : "+f"(acc[mt][nt][0]), "+f"(acc[mt][nt][1]),
                          "+f"(acc[mt][nt][2]), "+f"(acc[mt][nt][3])
                        : "r"(af[mt][0]), "r"(af[mt][1]),
                          "r"(af[mt][2]), "r"(af[mt][3]),
                          "r"(bf[nt][0]), "r"(bf[nt][1]));
        }
        __syncthreads();
    }

    #pragma unroll
    for (int mt = 0; mt < 4; mt++) {
        int r0 = block_row + warp_m * 64 + mt * 16 + (lane >> 2);
        #pragma unroll
        for (int half = 0; half < 2; half++) {
            int row = r0 + half * 8;
            if (row >= NN) continue;
            #pragma unroll
            for (int nt = 0; nt < 4; nt++) {
                int col = block_col + warp_n * 32 + nt * 8 + (lane & 3) * 2;
                float v0 = acc[mt][nt][half * 2 + 0];
                float v1 = acc[mt][nt][half * 2 + 1];
                if (LAYER1) {
                    v0 = fmaxf(v0 + bias[col],     0.f);
                    v1 = fmaxf(v1 + bias[col + 1], 0.f);
                }
                *(float2*)&C[(size_t)row * N + col] = make_float2(v0, v1);
            }
        }
    }
}

// ---------------- launch ------------------------------------------------------
extern "C" void kernel_launch(void* const* d_in, const int* in_sizes, int n_in,
                              void* d_out, int out_size) {
    const float* x  = (const float*)d_in[0];
    const int*   ei = (const int*)d_in[1];    // int32 (JAX x64 disabled)
    const float* W1 = (const float*)d_in[2];
    const float* b1 = (const float*)d_in[3];
    const float* W2 = (const float*)d_in[4];
    const float* b2 = (const float*)d_in[5];
    float* out = (float*)d_out;

    const int* srcp = ei;        // edge_index[0]
    const int* dstp = ei + NE;   // edge_index[1]

    const int T = 256;
    const int MBLK = (NN + 127) / 128;   // 391
    const int AGGR_GRID = (NN * 32 + T - 1) / T;

    // CSR build + normalization (multi-block scan)
    k_zero     <<<(NN + T - 1) / T, T>>>();
    k_count_deg<<<(NE + T - 1) / T, T>>>(dstp);
    k_dinv     <<<(NN + T - 1) / T, T>>>();
    k_scan1    <<<NB, 1024>>>();
    k_scan2    <<<1, 64>>>();
    k_scan3    <<<NB, 1024>>>();
    k_fill     <<<(NE + T - 1) / T, T>>>(srcp, dstp);

    // layer 1: agg1 = A_norm @ x ; h1 = relu(agg1 @ W1 + b1)
    k_aggr<false><<<AGGR_GRID, T>>>(x, nullptr, nullptr);
    {
        dim3 grid(FHID / 128, MBLK);
        mma_gemm<true><<<grid, 256>>>(W1, b1);
    }

    // layer 2: t2 = h1 @ W2 ; out = relu(A_norm @ t2 + b2)
    {
        dim3 grid(FOUT / 128, MBLK);
        mma_gemm<false><<<grid, 256>>>(W2, nullptr);
    }
    k_aggr<true><<<AGGR_GRID, T>>>(nullptr, b2, out);
}